// round 10
// baseline (speedup 1.0000x reference)
#include <cuda_runtime.h>
#include <cuda_fp16.h>
#include <math.h>
#include <stdint.h>

// Problem constants
#define Bn 64
#define Tn 256
#define En 1024
#define Hn 16
#define HDn 64
#define Mrows (Bn*Tn)          // 16384
#define QKV_N (3*En)           // 3072
#define Kdim 1024              // all GEMMs have K=1024

// ---------------- scratch (static device globals; no allocation) ----------------
__device__ __half g_h16[(size_t)Mrows*En];
__device__ __half g_qkv16[(size_t)Mrows*QKV_N];
__device__ __half g_attn16[(size_t)Mrows*En];
__device__ float  g_x1[(size_t)Mrows*En];
__device__ __half g_ff116[(size_t)Mrows*En];
// weights fp16, B-operand layout [N,K] K-major
__device__ __half g_wqkv[(size_t)QKV_N*Kdim];
__device__ __half g_wp[(size_t)En*Kdim];
__device__ __half g_w1[(size_t)En*Kdim];
__device__ __half g_w2[(size_t)En*Kdim];

// ---------------- small helpers ----------------
__device__ __forceinline__ uint32_t smem_u32(const void* p) {
    uint32_t a;
    asm("{ .reg .u64 t; cvta.to.shared.u64 t, %1; cvt.u32.u64 %0, t; }" : "=r"(a) : "l"(p));
    return a;
}
__device__ __forceinline__ uint32_t pack_h2(__half lo, __half hi) {
    __half2 t = __halves2half2(lo, hi);
    return *reinterpret_cast<uint32_t*>(&t);
}

#define CP_ASYNC16(dst, src) \
    asm volatile("cp.async.cg.shared.global [%0], [%1], 16;" :: "r"(dst), "l"(src) : "memory")
#define CP_COMMIT() asm volatile("cp.async.commit_group;" ::: "memory")
#define CP_WAIT1()  asm volatile("cp.async.wait_group 1;" ::: "memory")
#define CP_WAIT0()  asm volatile("cp.async.wait_group 0;" ::: "memory")

#define LDMX4(r, addr) \
    asm volatile("ldmatrix.sync.aligned.m8n8.x4.shared.b16 {%0,%1,%2,%3}, [%4];" \
        : "=r"((r)[0]),"=r"((r)[1]),"=r"((r)[2]),"=r"((r)[3]) : "r"(addr))
#define LDMX4T(r, addr) \
    asm volatile("ldmatrix.sync.aligned.m8n8.x4.trans.shared.b16 {%0,%1,%2,%3}, [%4];" \
        : "=r"((r)[0]),"=r"((r)[1]),"=r"((r)[2]),"=r"((r)[3]) : "r"(addr))

#define MMA16816(d, a, b0, b1) \
    asm volatile("mma.sync.aligned.m16n8k16.row.col.f32.f16.f16.f32 " \
        "{%0,%1,%2,%3},{%4,%5,%6,%7},{%8,%9},{%0,%1,%2,%3};" \
        : "+f"((d)[0]),"+f"((d)[1]),"+f"((d)[2]),"+f"((d)[3]) \
        : "r"((a)[0]),"r"((a)[1]),"r"((a)[2]),"r"((a)[3]), "r"(b0),"r"(b1))

// ---------------- LayerNorm -> fp16 ----------------
__device__ __forceinline__ float block_reduce_sum(float v, float* sbuf) {
    #pragma unroll
    for (int o = 16; o > 0; o >>= 1) v += __shfl_xor_sync(0xffffffffu, v, o);
    int w = threadIdx.x >> 5;
    if ((threadIdx.x & 31) == 0) sbuf[w] = v;
    __syncthreads();
    if (threadIdx.x < 8) {
        float t = sbuf[threadIdx.x];
        #pragma unroll
        for (int o = 4; o > 0; o >>= 1) t += __shfl_xor_sync(0xffu, t, o);
        if (threadIdx.x == 0) sbuf[0] = t;
    }
    __syncthreads();
    float r = sbuf[0];
    __syncthreads();
    return r;
}

__global__ __launch_bounds__(256) void ln_kernel(
    const float* __restrict__ x, const float* __restrict__ g,
    const float* __restrict__ b, __half* __restrict__ oh)
{
    __shared__ float sbuf[8];
    int row = blockIdx.x;
    const float* xr = x + (size_t)row * En;
    int tid = threadIdx.x;
    float4 xv = *(const float4*)(xr + tid * 4);
    float s = xv.x + xv.y + xv.z + xv.w;
    s = block_reduce_sum(s, sbuf);
    float mu = s * (1.0f / En);
    float d0 = xv.x - mu, d1 = xv.y - mu, d2 = xv.z - mu, d3 = xv.w - mu;
    float ss = d0*d0 + d1*d1 + d2*d2 + d3*d3;
    ss = block_reduce_sum(ss, sbuf);
    float rstd = rsqrtf(ss * (1.0f / En) + 1e-5f);
    float4 gv = *(const float4*)(g + tid * 4);
    float4 bv = *(const float4*)(b + tid * 4);
    float o0 = d0 * rstd * gv.x + bv.x;
    float o1 = d1 * rstd * gv.y + bv.y;
    float o2 = d2 * rstd * gv.z + bv.z;
    float o3 = d3 * rstd * gv.w + bv.w;
    size_t base = (size_t)row * En + tid * 4;
    *(__half2*)(oh + base)     = __halves2half2(__float2half_rn(o0), __float2half_rn(o1));
    *(__half2*)(oh + base + 2) = __halves2half2(__float2half_rn(o2), __float2half_rn(o3));
}

// ---------------- weight transpose-convert: W[K,N] fp32 -> B[N,K] fp16 ----------------
__global__ __launch_bounds__(1024) void tconv_kernel(
    const float* __restrict__ W, __half* __restrict__ Bh, int K, int N)
{
    __shared__ float tile[32][33];
    int tx = threadIdx.x & 31, ty = threadIdx.x >> 5;
    int k = blockIdx.y * 32 + ty, n = blockIdx.x * 32 + tx;
    tile[ty][tx] = W[(size_t)k * N + n];
    __syncthreads();
    int nn = blockIdx.x * 32 + ty, kk = blockIdx.y * 32 + tx;
    Bh[(size_t)nn * K + kk] = __float2half_rn(tile[tx][ty]);
}

// qkv pack: wk/wq/wv [H,E,HD] -> B[3072,1024] rows n = which*1024 + h*64 + d, col e
__global__ __launch_bounds__(1024) void pack_qkv_kernel(
    const float* __restrict__ wk, const float* __restrict__ wq,
    const float* __restrict__ wv, __half* __restrict__ Bh)
{
    __shared__ float tile[32][33];
    int tx = threadIdx.x & 31, ty = threadIdx.x >> 5;
    int wh = blockIdx.z;             // which*16 + h
    int which = wh >> 4, h = wh & 15;
    const float* src = (which == 0) ? wk : (which == 1) ? wq : wv;
    int e = blockIdx.y * 32 + ty;
    int d = blockIdx.x * 32 + tx;
    tile[ty][tx] = src[(size_t)h * (En * HDn) + (size_t)e * HDn + d];
    __syncthreads();
    int n = which * En + h * HDn + blockIdx.x * 32 + ty;
    int ee = blockIdx.y * 32 + tx;
    Bh[(size_t)n * Kdim + ee] = __float2half_rn(tile[tx][ty]);
}

// ---------------- HMMA GEMM: C[M,N] = A[M,1024] @ B[N,1024]^T, fp16 single ----------------
// CTA tile 128xBN, 8 warps (2x4), warp tile 64x(BN/4). K chunks of 32, 3-stage cp.async.
#define TPITCH   80
#define A_TILE_B (128*TPITCH)     // 10240
#define NCHUNK   (Kdim/32)        // 32

template <int BN>
__global__ __launch_bounds__(256, 2) void mma_gemm_kernel(
    const __half* __restrict__ Am, const __half* __restrict__ Bw,
    const float* __restrict__ bias, const float* __restrict__ res, int relu,
    float* __restrict__ outF, __half* __restrict__ outH, int N)
{
    constexpr int WN = BN / 4;         // warp N-tile (32 or 16)
    constexpr int FN = WN / 8;         // n8 frags per warp (4 or 2)
    constexpr int B_TILE_B = BN * TPITCH;
    constexpr int STAGE_B  = A_TILE_B + B_TILE_B;

    extern __shared__ char smem[];
    uint32_t sb = smem_u32(smem);
    int tid  = threadIdx.x;
    int lane = tid & 31, wid = tid >> 5;
    int wm = wid >> 2, wn = wid & 3;      // warp grid 2x4
    int row0 = blockIdx.y * 128, col0 = blockIdx.x * BN;

    const __half* srcA = Am + (size_t)row0 * Kdim;
    const __half* srcB = Bw + (size_t)col0 * Kdim;

    float acc[4][FN][4];
    #pragma unroll
    for (int i = 0; i < 4; i++)
        #pragma unroll
        for (int j = 0; j < FN; j++)
            #pragma unroll
            for (int q = 0; q < 4; q++) acc[i][j][q] = 0.0f;

    int rowsel = lane & 15;
    int ghalf  = lane >> 4;
    uint32_t aRowOff = (uint32_t)((wm * 64 + rowsel) * TPITCH);
    uint32_t bRowOff = (uint32_t)((wn * WN + rowsel % WN) * TPITCH);
    // note: for WN=16 rowsel spans 0..15 which == rows of the n16 ldmatrix block

    #define LOAD_CHUNK(c) do { \
        int k0 = (c) * 32; \
        uint32_t bb = sb + ((c) % 3) * STAGE_B; \
        _Pragma("unroll") \
        for (int i = tid; i < 512; i += 256) { \
            int r = i >> 2, g = i & 3; \
            CP_ASYNC16(bb + (uint32_t)(r * TPITCH + g * 16), srcA + (size_t)r * Kdim + g * 8 + k0); \
        } \
        _Pragma("unroll") \
        for (int i = tid; i < BN * 4; i += 256) { \
            int r = i >> 2, g = i & 3; \
            CP_ASYNC16(bb + A_TILE_B + (uint32_t)(r * TPITCH + g * 16), srcB + (size_t)r * Kdim + g * 8 + k0); \
        } \
        CP_COMMIT(); \
    } while (0)

    LOAD_CHUNK(0);
    LOAD_CHUNK(1);

    for (int c = 0; c < NCHUNK; c++) {
        if (c + 1 < NCHUNK) CP_WAIT1(); else CP_WAIT0();
        __syncthreads();
        if (c + 2 < NCHUNK) LOAD_CHUNK(c + 2);

        uint32_t bb = sb + (c % 3) * STAGE_B;
        #pragma unroll
        for (int ks = 0; ks < 2; ks++) {
            uint32_t kOff = (uint32_t)((ks * 2 + ghalf) * 16);
            uint32_t fA[4][4], fB[WN / 16][4];
            #pragma unroll
            for (int fm = 0; fm < 4; fm++) {
                uint32_t ra = bb + aRowOff + (uint32_t)(fm * 16 * TPITCH) + kOff;
                LDMX4(fA[fm], ra);
            }
            #pragma unroll
            for (int h = 0; h < WN / 16; h++) {
                uint32_t rb = bb + A_TILE_B + bRowOff + (uint32_t)(h * 16 * TPITCH) + kOff;
                LDMX4(fB[h], rb);
            }
            #pragma unroll
            for (int fm = 0; fm < 4; fm++)
                #pragma unroll
                for (int fn = 0; fn < FN; fn++) {
                    int h = fn >> 1, s2 = fn & 1;
                    MMA16816(acc[fm][fn], fA[fm], fB[h][s2], fB[h][s2 + 2]);
                }
        }
    }
    #undef LOAD_CHUNK
    __syncthreads();

    // epilogue
    #pragma unroll
    for (int fm = 0; fm < 4; fm++) {
        #pragma unroll
        for (int fn = 0; fn < FN; fn++) {
            int r = row0 + wm * 64 + fm * 16 + (lane >> 2);
            int cc = col0 + wn * WN + fn * 8 + 2 * (lane & 3);
            #pragma unroll
            for (int hf = 0; hf < 2; hf++) {
                int rr = r + hf * 8;
                float v0 = acc[fm][fn][hf * 2 + 0];
                float v1 = acc[fm][fn][hf * 2 + 1];
                if (bias) {
                    float2 bv = *(const float2*)(bias + cc);
                    v0 += bv.x; v1 += bv.y;
                }
                if (res) {
                    float2 rv = *(const float2*)(res + (size_t)rr * N + cc);
                    v0 += rv.x; v1 += rv.y;
                }
                if (relu) { v0 = fmaxf(v0, 0.f); v1 = fmaxf(v1, 0.f); }
                if (outF) {
                    *(float2*)(outF + (size_t)rr * N + cc) = make_float2(v0, v1);
                } else {
                    *(__half2*)(outH + (size_t)rr * N + cc) =
                        __halves2half2(__float2half_rn(v0), __float2half_rn(v1));
                }
            }
        }
    }
}

#define GEMM_SMEM_128 (3*(A_TILE_B + 128*TPITCH))  // 61440
#define GEMM_SMEM_64  (3*(A_TILE_B + 64*TPITCH))   // 46080

// ---------------- MMA flash attention (scores = K . Q^T per reference) ----------------
// One CTA per (b,h). smem: 3 tiles [256 x 64] fp16, pitch 72 halfs (144B): K, Q, V.
#define APITCHB 144
#define ATILE   (256*APITCHB)   // 36864
#define ATTN_SMEM (3*ATILE)     // 110592

__global__ __launch_bounds__(256, 2) void attn_mma_kernel(
    const __half* __restrict__ qkv16, __half* __restrict__ outH)
{
    extern __shared__ char smem[];
    uint32_t sb = smem_u32(smem);
    int bh = blockIdx.x;
    int b = bh >> 4, h = bh & 15;
    int tid = threadIdx.x, lane = tid & 31, wid = tid >> 5;

    const size_t rowBase = (size_t)(b * Tn) * QKV_N;
    {
        const __half* srcs[3] = {
            qkv16 + rowBase + h * 64,
            qkv16 + rowBase + 1024 + h * 64,
            qkv16 + rowBase + 2048 + h * 64 };
        #pragma unroll
        for (int tl = 0; tl < 3; tl++) {
            uint32_t tb = sb + tl * ATILE;
            const __half* s = srcs[tl];
            #pragma unroll
            for (int i = 0; i < 8; i++) {
                int idx = i * 256 + tid;
                int r = idx >> 3, g = idx & 7;
                CP_ASYNC16(tb + (uint32_t)(r * APITCHB + g * 16), s + (size_t)r * QKV_N + g * 8);
            }
        }
        CP_COMMIT(); CP_WAIT0();
        __syncthreads();
    }
    uint32_t tK = sb, tQ = sb + ATILE, tV = sb + 2*ATILE;

    const float scale = 0.125f;
    int rsel = lane & 15, ghalf = lane >> 4;
    int lr = lane >> 2, lq = lane & 3;

    #pragma unroll
    for (int hb = 0; hb < 2; hb++) {
        int tb = (hb == 0) ? wid : 15 - wid;
        uint32_t kA[4][4];
        {
            uint32_t rowoff = (uint32_t)((tb * 16 + rsel) * APITCHB);
            #pragma unroll
            for (int k = 0; k < 4; k++) {
                uint32_t coff = (uint32_t)((k * 16 + ghalf * 8) * 2);
                LDMX4(kA[k], tK + rowoff + coff);
            }
        }
        float accO[8][4];
        #pragma unroll
        for (int n = 0; n < 8; n++)
            #pragma unroll
            for (int e = 0; e < 4; e++) accO[n][e] = 0.0f;
        float mrow0 = -1e30f, mrow1 = -1e30f, lrow0 = 0.0f, lrow1 = 0.0f;

        for (int sbk = 0; sbk <= tb; sbk++) {
            float S[2][4];
            #pragma unroll
            for (int j = 0; j < 2; j++)
                #pragma unroll
                for (int e = 0; e < 4; e++) S[j][e] = 0.0f;
            uint32_t rowoffS = (uint32_t)((sbk * 16 + rsel) * APITCHB);
            #pragma unroll
            for (int k = 0; k < 4; k++) {
                uint32_t coff = (uint32_t)((k * 16 + ghalf * 8) * 2);
                uint32_t qf[4];
                LDMX4(qf, tQ + rowoffS + coff);
                MMA16816(S[0], kA[k], qf[0], qf[2]);
                MMA16816(S[1], kA[k], qf[1], qf[3]);
            }
            #pragma unroll
            for (int j = 0; j < 2; j++)
                #pragma unroll
                for (int e = 0; e < 4; e++) {
                    float v = S[j][e] * scale;
                    if (sbk == tb) {
                        int row = tb * 16 + lr + ((e >> 1) << 3);
                        int col = sbk * 16 + j * 8 + 2 * lq + (e & 1);
                        if (col > row) v = -1e30f;
                    }
                    S[j][e] = v;
                }
            float mx0 = fmaxf(fmaxf(S[0][0], S[0][1]), fmaxf(S[1][0], S[1][1]));
            float mx1 = fmaxf(fmaxf(S[0][2], S[0][3]), fmaxf(S[1][2], S[1][3]));
            mx0 = fmaxf(mx0, __shfl_xor_sync(0xffffffffu, mx0, 1));
            mx0 = fmaxf(mx0, __shfl_xor_sync(0xffffffffu, mx0, 2));
            mx1 = fmaxf(mx1, __shfl_xor_sync(0xffffffffu, mx1, 1));
            mx1 = fmaxf(mx1, __shfl_xor_sync(0xffffffffu, mx1, 2));
            float mn0 = fmaxf(mrow0, mx0), mn1 = fmaxf(mrow1, mx1);
            float c0 = __expf(mrow0 - mn0), c1 = __expf(mrow1 - mn1);
            mrow0 = mn0; mrow1 = mn1;
            float p00 = __expf(S[0][0] - mn0), p01 = __expf(S[0][1] - mn0);
            float p10 = __expf(S[1][0] - mn0), p11 = __expf(S[1][1] - mn0);
            float p02 = __expf(S[0][2] - mn1), p03 = __expf(S[0][3] - mn1);
            float p12 = __expf(S[1][2] - mn1), p13 = __expf(S[1][3] - mn1);
            float sum0 = p00 + p01 + p10 + p11;
            float sum1 = p02 + p03 + p12 + p13;
            sum0 += __shfl_xor_sync(0xffffffffu, sum0, 1);
            sum0 += __shfl_xor_sync(0xffffffffu, sum0, 2);
            sum1 += __shfl_xor_sync(0xffffffffu, sum1, 1);
            sum1 += __shfl_xor_sync(0xffffffffu, sum1, 2);
            lrow0 = lrow0 * c0 + sum0;
            lrow1 = lrow1 * c1 + sum1;
            #pragma unroll
            for (int n = 0; n < 8; n++) {
                accO[n][0] *= c0; accO[n][1] *= c0;
                accO[n][2] *= c1; accO[n][3] *= c1;
            }
            uint32_t pA[4] = {
                pack_h2(__float2half_rn(p00), __float2half_rn(p01)),
                pack_h2(__float2half_rn(p02), __float2half_rn(p03)),
                pack_h2(__float2half_rn(p10), __float2half_rn(p11)),
                pack_h2(__float2half_rn(p12), __float2half_rn(p13)) };
            #pragma unroll
            for (int dp = 0; dp < 4; dp++) {
                uint32_t coff = (uint32_t)((dp * 16 + ghalf * 8) * 2);
                uint32_t vf[4];
                LDMX4T(vf, tV + rowoffS + coff);
                MMA16816(accO[dp*2],   pA, vf[0], vf[1]);
                MMA16816(accO[dp*2+1], pA, vf[2], vf[3]);
            }
        }
        float inv0 = 1.0f / lrow0, inv1 = 1.0f / lrow1;
        int rowA = b * Tn + tb * 16 + lr;
        int rowB = rowA + 8;
        #pragma unroll
        for (int n = 0; n < 8; n++) {
            int d = h * 64 + n * 8 + 2 * lq;
            float v0 = accO[n][0] * inv0, v1 = accO[n][1] * inv0;
            float v2 = accO[n][2] * inv1, v3 = accO[n][3] * inv1;
            *(__half2*)(outH + (size_t)rowA * En + d) =
                __halves2half2(__float2half_rn(v0), __float2half_rn(v1));
            *(__half2*)(outH + (size_t)rowB * En + d) =
                __halves2half2(__float2half_rn(v2), __float2half_rn(v3));
        }
    }
}

// ---------------- launch ----------------
extern "C" void kernel_launch(void* const* d_in, const int* in_sizes, int n_in,
                              void* d_out, int out_size)
{
    const float* x      = (const float*)d_in[0];
    const float* ln1_g  = (const float*)d_in[1];
    const float* ln1_b  = (const float*)d_in[2];
    const float* wk     = (const float*)d_in[3];
    const float* wq     = (const float*)d_in[4];
    const float* wv     = (const float*)d_in[5];
    const float* w_proj = (const float*)d_in[6];
    const float* b_proj = (const float*)d_in[7];
    const float* ln2_g  = (const float*)d_in[8];
    const float* ln2_b  = (const float*)d_in[9];
    const float* w1     = (const float*)d_in[10];
    const float* b1     = (const float*)d_in[11];
    const float* w2     = (const float*)d_in[12];
    const float* b2     = (const float*)d_in[13];
    float* out = (float*)d_out;

    void* p;
    __half *h16,*qkv16,*attn16,*ff116,*wqkv,*wp,*w1h,*w2h;
    float *x1;
    cudaGetSymbolAddress(&p, g_h16);    h16    = (__half*)p;
    cudaGetSymbolAddress(&p, g_qkv16);  qkv16  = (__half*)p;
    cudaGetSymbolAddress(&p, g_attn16); attn16 = (__half*)p;
    cudaGetSymbolAddress(&p, g_x1);     x1     = (float*)p;
    cudaGetSymbolAddress(&p, g_ff116);  ff116  = (__half*)p;
    cudaGetSymbolAddress(&p, g_wqkv);   wqkv   = (__half*)p;
    cudaGetSymbolAddress(&p, g_wp);     wp     = (__half*)p;
    cudaGetSymbolAddress(&p, g_w1);     w1h    = (__half*)p;
    cudaGetSymbolAddress(&p, g_w2);     w2h    = (__half*)p;

    cudaFuncSetAttribute(attn_mma_kernel, cudaFuncAttributeMaxDynamicSharedMemorySize, ATTN_SMEM);
    cudaFuncSetAttribute(mma_gemm_kernel<128>, cudaFuncAttributeMaxDynamicSharedMemorySize, GEMM_SMEM_128);
    cudaFuncSetAttribute(mma_gemm_kernel<64>,  cudaFuncAttributeMaxDynamicSharedMemorySize, GEMM_SMEM_64);

    // 1) LN1 -> fp16
    ln_kernel<<<Mrows, 256>>>(x, ln1_g, ln1_b, h16);
    // 2) weight conversions (fp16)
    pack_qkv_kernel<<<dim3(2, 32, 48), 1024>>>(wk, wq, wv, wqkv);
    tconv_kernel<<<dim3(32, 32), 1024>>>(w_proj, wp, Kdim, En);
    tconv_kernel<<<dim3(32, 32), 1024>>>(w1, w1h, Kdim, En);
    tconv_kernel<<<dim3(32, 32), 1024>>>(w2, w2h, Kdim, En);
    // 3) QKV GEMM -> fp16 qkv (BN=128: 24x128 grid, 10.4 waves, tail 6%)
    mma_gemm_kernel<128><<<dim3(QKV_N/128, Mrows/128), 256, GEMM_SMEM_128>>>(
        h16, wqkv, nullptr, nullptr, 0, nullptr, qkv16, QKV_N);
    // 4) MMA flash attention -> fp16 (2 CTAs/SM)
    attn_mma_kernel<<<Bn * Hn, 256, ATTN_SMEM>>>(qkv16, attn16);
    // 5) proj + bias + residual(x) -> fp32 x1 (BN=64: 16x128 grid, tail ~1%)
    mma_gemm_kernel<64><<<dim3(En/64, Mrows/128), 256, GEMM_SMEM_64>>>(
        attn16, wp, b_proj, x, 0, x1, nullptr, En);
    // 6) LN2 -> fp16
    ln_kernel<<<Mrows, 256>>>(x1, ln2_g, ln2_b, h16);
    // 7) FFN1 + bias + relu -> fp16
    mma_gemm_kernel<64><<<dim3(En/64, Mrows/128), 256, GEMM_SMEM_64>>>(
        h16, w1h, b1, nullptr, 1, nullptr, ff116, En);
    // 8) FFN2 + bias + residual(x1) -> out
    mma_gemm_kernel<64><<<dim3(En/64, Mrows/128), 256, GEMM_SMEM_64>>>(
        ff116, w2h, b2, x1, 0, out, nullptr, En);
}

// round 14
// speedup vs baseline: 1.0718x; 1.0718x over previous
#include <cuda_runtime.h>
#include <cuda_fp16.h>
#include <math.h>
#include <stdint.h>

// Problem constants
#define Bn 64
#define Tn 256
#define En 1024
#define Hn 16
#define HDn 64
#define Mrows (Bn*Tn)          // 16384
#define QKV_N (3*En)           // 3072
#define Kdim 1024              // all GEMMs have K=1024

// ---------------- scratch (static device globals; no allocation) ----------------
__device__ __half g_h16[(size_t)Mrows*En];
__device__ __half g_qkv16[(size_t)Mrows*QKV_N];
__device__ __half g_attn16[(size_t)Mrows*En];
__device__ float  g_x1[(size_t)Mrows*En];
__device__ __half g_ff116[(size_t)Mrows*En];
// weights fp16, B-operand layout [N,K] K-major
__device__ __half g_wqkv[(size_t)QKV_N*Kdim];
__device__ __half g_wp[(size_t)En*Kdim];
__device__ __half g_w1[(size_t)En*Kdim];
__device__ __half g_w2[(size_t)En*Kdim];

// ---------------- small helpers ----------------
__device__ __forceinline__ uint32_t smem_u32(const void* p) {
    uint32_t a;
    asm("{ .reg .u64 t; cvta.to.shared.u64 t, %1; cvt.u32.u64 %0, t; }" : "=r"(a) : "l"(p));
    return a;
}
__device__ __forceinline__ uint32_t pack_h2(__half lo, __half hi) {
    __half2 t = __halves2half2(lo, hi);
    return *reinterpret_cast<uint32_t*>(&t);
}

#define CP_ASYNC16(dst, src) \
    asm volatile("cp.async.cg.shared.global [%0], [%1], 16;" :: "r"(dst), "l"(src) : "memory")
#define CP_COMMIT() asm volatile("cp.async.commit_group;" ::: "memory")
#define CP_WAIT1()  asm volatile("cp.async.wait_group 1;" ::: "memory")
#define CP_WAIT0()  asm volatile("cp.async.wait_group 0;" ::: "memory")

#define LDMX4(r, addr) \
    asm volatile("ldmatrix.sync.aligned.m8n8.x4.shared.b16 {%0,%1,%2,%3}, [%4];" \
        : "=r"((r)[0]),"=r"((r)[1]),"=r"((r)[2]),"=r"((r)[3]) : "r"(addr))
#define LDMX4T(r, addr) \
    asm volatile("ldmatrix.sync.aligned.m8n8.x4.trans.shared.b16 {%0,%1,%2,%3}, [%4];" \
        : "=r"((r)[0]),"=r"((r)[1]),"=r"((r)[2]),"=r"((r)[3]) : "r"(addr))

#define MMA16816(d, a, b0, b1) \
    asm volatile("mma.sync.aligned.m16n8k16.row.col.f32.f16.f16.f32 " \
        "{%0,%1,%2,%3},{%4,%5,%6,%7},{%8,%9},{%0,%1,%2,%3};" \
        : "+f"((d)[0]),"+f"((d)[1]),"+f"((d)[2]),"+f"((d)[3]) \
        : "r"((a)[0]),"r"((a)[1]),"r"((a)[2]),"r"((a)[3]), "r"(b0),"r"(b1))

// ---------------- LayerNorm -> fp16 ----------------
__device__ __forceinline__ float block_reduce_sum(float v, float* sbuf) {
    #pragma unroll
    for (int o = 16; o > 0; o >>= 1) v += __shfl_xor_sync(0xffffffffu, v, o);
    int w = threadIdx.x >> 5;
    if ((threadIdx.x & 31) == 0) sbuf[w] = v;
    __syncthreads();
    if (threadIdx.x < 8) {
        float t = sbuf[threadIdx.x];
        #pragma unroll
        for (int o = 4; o > 0; o >>= 1) t += __shfl_xor_sync(0xffu, t, o);
        if (threadIdx.x == 0) sbuf[0] = t;
    }
    __syncthreads();
    float r = sbuf[0];
    __syncthreads();
    return r;
}

__global__ __launch_bounds__(256) void ln_kernel(
    const float* __restrict__ x, const float* __restrict__ g,
    const float* __restrict__ b, __half* __restrict__ oh)
{
    __shared__ float sbuf[8];
    int row = blockIdx.x;
    const float* xr = x + (size_t)row * En;
    int tid = threadIdx.x;
    float4 xv = *(const float4*)(xr + tid * 4);
    float s = xv.x + xv.y + xv.z + xv.w;
    s = block_reduce_sum(s, sbuf);
    float mu = s * (1.0f / En);
    float d0 = xv.x - mu, d1 = xv.y - mu, d2 = xv.z - mu, d3 = xv.w - mu;
    float ss = d0*d0 + d1*d1 + d2*d2 + d3*d3;
    ss = block_reduce_sum(ss, sbuf);
    float rstd = rsqrtf(ss * (1.0f / En) + 1e-5f);
    float4 gv = *(const float4*)(g + tid * 4);
    float4 bv = *(const float4*)(b + tid * 4);
    float o0 = d0 * rstd * gv.x + bv.x;
    float o1 = d1 * rstd * gv.y + bv.y;
    float o2 = d2 * rstd * gv.z + bv.z;
    float o3 = d3 * rstd * gv.w + bv.w;
    size_t base = (size_t)row * En + tid * 4;
    *(__half2*)(oh + base)     = __halves2half2(__float2half_rn(o0), __float2half_rn(o1));
    *(__half2*)(oh + base + 2) = __halves2half2(__float2half_rn(o2), __float2half_rn(o3));
}

// ---------------- merged weight transpose-convert: 3x W[1024,1024] -> B[N,K] fp16 ----------------
__global__ __launch_bounds__(1024) void tconv3_kernel(
    const float* __restrict__ W0, __half* __restrict__ B0,
    const float* __restrict__ W1, __half* __restrict__ B1,
    const float* __restrict__ W2, __half* __restrict__ B2)
{
    __shared__ float tile[32][33];
    const float* W = (blockIdx.z == 0) ? W0 : (blockIdx.z == 1) ? W1 : W2;
    __half* Bh     = (blockIdx.z == 0) ? B0 : (blockIdx.z == 1) ? B1 : B2;
    int tx = threadIdx.x & 31, ty = threadIdx.x >> 5;
    int k = blockIdx.y * 32 + ty, n = blockIdx.x * 32 + tx;
    tile[ty][tx] = W[(size_t)k * En + n];
    __syncthreads();
    int nn = blockIdx.x * 32 + ty, kk = blockIdx.y * 32 + tx;
    Bh[(size_t)nn * Kdim + kk] = __float2half_rn(tile[tx][ty]);
}

// qkv pack: wk/wq/wv [H,E,HD] -> B[3072,1024] rows n = which*1024 + h*64 + d, col e
__global__ __launch_bounds__(1024) void pack_qkv_kernel(
    const float* __restrict__ wk, const float* __restrict__ wq,
    const float* __restrict__ wv, __half* __restrict__ Bh)
{
    __shared__ float tile[32][33];
    int tx = threadIdx.x & 31, ty = threadIdx.x >> 5;
    int wh = blockIdx.z;             // which*16 + h
    int which = wh >> 4, h = wh & 15;
    const float* src = (which == 0) ? wk : (which == 1) ? wq : wv;
    int e = blockIdx.y * 32 + ty;
    int d = blockIdx.x * 32 + tx;
    tile[ty][tx] = src[(size_t)h * (En * HDn) + (size_t)e * HDn + d];
    __syncthreads();
    int n = which * En + h * HDn + blockIdx.x * 32 + ty;
    int ee = blockIdx.y * 32 + tx;
    Bh[(size_t)n * Kdim + ee] = __float2half_rn(tile[tx][ty]);
}

// ---------------- HMMA GEMM: C[M,N] = A[M,1024] @ B[N,1024]^T, fp16 single ----------------
// CTA tile 128x128, 8 warps (2x4), warp tile 64x32. K chunks of 32, 3-stage cp.async.
#define TPITCH   80
#define TILE_B   (128*TPITCH)     // 10240
#define STAGE_B  (2*TILE_B)       // 20480: A, B
#define NCHUNK   (Kdim/32)        // 32
#define GEMM_SMEM (3*STAGE_B)     // 61440

__global__ __launch_bounds__(256, 2) void mma_gemm_kernel(
    const __half* __restrict__ Am, const __half* __restrict__ Bw,
    const float* __restrict__ bias, const float* __restrict__ res, int relu,
    float* __restrict__ outF, __half* __restrict__ outH, int N)
{
    extern __shared__ char smem[];
    uint32_t sb = smem_u32(smem);
    int tid  = threadIdx.x;
    int lane = tid & 31, wid = tid >> 5;
    int wm = wid >> 2, wn = wid & 3;      // warp grid 2x4
    int row0 = blockIdx.y * 128, col0 = blockIdx.x * 128;

    const __half* srcA = Am + (size_t)row0 * Kdim;
    const __half* srcB = Bw + (size_t)col0 * Kdim;

    int id0 = tid, id1 = tid + 256;
    int r0g = id0 >> 2, g0 = id0 & 3;
    int r1g = id1 >> 2, g1 = id1 & 3;
    uint32_t so0 = (uint32_t)(r0g * TPITCH + g0 * 16);
    uint32_t so1 = (uint32_t)(r1g * TPITCH + g1 * 16);
    size_t   go0 = (size_t)r0g * Kdim + g0 * 8;
    size_t   go1 = (size_t)r1g * Kdim + g1 * 8;

    float acc[4][4][4];
    #pragma unroll
    for (int i = 0; i < 4; i++)
        #pragma unroll
        for (int j = 0; j < 4; j++)
            #pragma unroll
            for (int q = 0; q < 4; q++) acc[i][j][q] = 0.0f;

    int rowsel = lane & 15;
    int ghalf  = lane >> 4;
    uint32_t aRowOff = (uint32_t)((wm * 64 + rowsel) * TPITCH);
    uint32_t bRowOff = (uint32_t)((wn * 32 + rowsel) * TPITCH);

    #define LOAD_CHUNK(c) do { \
        int k0 = (c) * 32; \
        uint32_t bb = sb + ((c) % 3) * STAGE_B; \
        CP_ASYNC16(bb + so0,          srcA + go0 + k0); \
        CP_ASYNC16(bb + so1,          srcA + go1 + k0); \
        CP_ASYNC16(bb + TILE_B + so0, srcB + go0 + k0); \
        CP_ASYNC16(bb + TILE_B + so1, srcB + go1 + k0); \
        CP_COMMIT(); \
    } while (0)

    LOAD_CHUNK(0);
    LOAD_CHUNK(1);

    for (int c = 0; c < NCHUNK; c++) {
        if (c + 1 < NCHUNK) CP_WAIT1(); else CP_WAIT0();
        __syncthreads();
        if (c + 2 < NCHUNK) LOAD_CHUNK(c + 2);

        uint32_t bb = sb + (c % 3) * STAGE_B;
        #pragma unroll
        for (int ks = 0; ks < 2; ks++) {
            uint32_t kOff = (uint32_t)((ks * 2 + ghalf) * 16);
            uint32_t fA[4][4], fB[2][4];
            #pragma unroll
            for (int fm = 0; fm < 4; fm++) {
                uint32_t ra = bb + aRowOff + (uint32_t)(fm * 16 * TPITCH) + kOff;
                LDMX4(fA[fm], ra);
            }
            #pragma unroll
            for (int h = 0; h < 2; h++) {
                uint32_t rb = bb + TILE_B + bRowOff + (uint32_t)(h * 16 * TPITCH) + kOff;
                LDMX4(fB[h], rb);
            }
            #pragma unroll
            for (int fm = 0; fm < 4; fm++)
                #pragma unroll
                for (int fn = 0; fn < 4; fn++) {
                    int h = fn >> 1, s2 = fn & 1;
                    MMA16816(acc[fm][fn], fA[fm], fB[h][s2], fB[h][s2 + 2]);
                }
        }
    }
    #undef LOAD_CHUNK
    __syncthreads();

    // epilogue
    #pragma unroll
    for (int fm = 0; fm < 4; fm++) {
        #pragma unroll
        for (int fn = 0; fn < 4; fn++) {
            int r = row0 + wm * 64 + fm * 16 + (lane >> 2);
            int cc = col0 + wn * 32 + fn * 8 + 2 * (lane & 3);
            #pragma unroll
            for (int hf = 0; hf < 2; hf++) {
                int rr = r + hf * 8;
                float v0 = acc[fm][fn][hf * 2 + 0];
                float v1 = acc[fm][fn][hf * 2 + 1];
                if (bias) {
                    float2 bv = *(const float2*)(bias + cc);
                    v0 += bv.x; v1 += bv.y;
                }
                if (res) {
                    float2 rv = *(const float2*)(res + (size_t)rr * N + cc);
                    v0 += rv.x; v1 += rv.y;
                }
                if (relu) { v0 = fmaxf(v0, 0.f); v1 = fmaxf(v1, 0.f); }
                if (outF) {
                    *(float2*)(outF + (size_t)rr * N + cc) = make_float2(v0, v1);
                } else {
                    *(__half2*)(outH + (size_t)rr * N + cc) =
                        __halves2half2(__float2half_rn(v0), __float2half_rn(v1));
                }
            }
        }
    }
}

// ---------------- MMA flash attention (scores = K . Q^T per reference) ----------------
// One CTA per (b,h). smem: 3 tiles [256 x 64] fp16, pitch 72 halfs (144B): K, Q, V.
#define APITCHB 144
#define ATILE   (256*APITCHB)   // 36864
#define ATTN_SMEM (3*ATILE)     // 110592

__global__ __launch_bounds__(256, 2) void attn_mma_kernel(
    const __half* __restrict__ qkv16, __half* __restrict__ outH)
{
    extern __shared__ char smem[];
    uint32_t sb = smem_u32(smem);
    int bh = blockIdx.x;
    int b = bh >> 4, h = bh & 15;
    int tid = threadIdx.x, lane = tid & 31, wid = tid >> 5;

    const size_t rowBase = (size_t)(b * Tn) * QKV_N;
    {
        const __half* srcs[3] = {
            qkv16 + rowBase + h * 64,
            qkv16 + rowBase + 1024 + h * 64,
            qkv16 + rowBase + 2048 + h * 64 };
        #pragma unroll
        for (int tl = 0; tl < 3; tl++) {
            uint32_t tb = sb + tl * ATILE;
            const __half* s = srcs[tl];
            #pragma unroll
            for (int i = 0; i < 8; i++) {
                int idx = i * 256 + tid;
                int r = idx >> 3, g = idx & 7;
                CP_ASYNC16(tb + (uint32_t)(r * APITCHB + g * 16), s + (size_t)r * QKV_N + g * 8);
            }
        }
        CP_COMMIT(); CP_WAIT0();
        __syncthreads();
    }
    uint32_t tK = sb, tQ = sb + ATILE, tV = sb + 2*ATILE;

    const float scale = 0.125f;
    int rsel = lane & 15, ghalf = lane >> 4;
    int lr = lane >> 2, lq = lane & 3;

    #pragma unroll
    for (int hb = 0; hb < 2; hb++) {
        int tb = (hb == 0) ? wid : 15 - wid;
        uint32_t kA[4][4];
        {
            uint32_t rowoff = (uint32_t)((tb * 16 + rsel) * APITCHB);
            #pragma unroll
            for (int k = 0; k < 4; k++) {
                uint32_t coff = (uint32_t)((k * 16 + ghalf * 8) * 2);
                LDMX4(kA[k], tK + rowoff + coff);
            }
        }
        float accO[8][4];
        #pragma unroll
        for (int n = 0; n < 8; n++)
            #pragma unroll
            for (int e = 0; e < 4; e++) accO[n][e] = 0.0f;
        float mrow0 = -1e30f, mrow1 = -1e30f, lrow0 = 0.0f, lrow1 = 0.0f;

        for (int sbk = 0; sbk <= tb; sbk++) {
            float S[2][4];
            #pragma unroll
            for (int j = 0; j < 2; j++)
                #pragma unroll
                for (int e = 0; e < 4; e++) S[j][e] = 0.0f;
            uint32_t rowoffS = (uint32_t)((sbk * 16 + rsel) * APITCHB);
            #pragma unroll
            for (int k = 0; k < 4; k++) {
                uint32_t coff = (uint32_t)((k * 16 + ghalf * 8) * 2);
                uint32_t qf[4];
                LDMX4(qf, tQ + rowoffS + coff);
                MMA16816(S[0], kA[k], qf[0], qf[2]);
                MMA16816(S[1], kA[k], qf[1], qf[3]);
            }
            #pragma unroll
            for (int j = 0; j < 2; j++)
                #pragma unroll
                for (int e = 0; e < 4; e++) {
                    float v = S[j][e] * scale;
                    if (sbk == tb) {
                        int row = tb * 16 + lr + ((e >> 1) << 3);
                        int col = sbk * 16 + j * 8 + 2 * lq + (e & 1);
                        if (col > row) v = -1e30f;
                    }
                    S[j][e] = v;
                }
            float mx0 = fmaxf(fmaxf(S[0][0], S[0][1]), fmaxf(S[1][0], S[1][1]));
            float mx1 = fmaxf(fmaxf(S[0][2], S[0][3]), fmaxf(S[1][2], S[1][3]));
            mx0 = fmaxf(mx0, __shfl_xor_sync(0xffffffffu, mx0, 1));
            mx0 = fmaxf(mx0, __shfl_xor_sync(0xffffffffu, mx0, 2));
            mx1 = fmaxf(mx1, __shfl_xor_sync(0xffffffffu, mx1, 1));
            mx1 = fmaxf(mx1, __shfl_xor_sync(0xffffffffu, mx1, 2));
            float mn0 = fmaxf(mrow0, mx0), mn1 = fmaxf(mrow1, mx1);
            float c0 = __expf(mrow0 - mn0), c1 = __expf(mrow1 - mn1);
            mrow0 = mn0; mrow1 = mn1;
            float p00 = __expf(S[0][0] - mn0), p01 = __expf(S[0][1] - mn0);
            float p10 = __expf(S[1][0] - mn0), p11 = __expf(S[1][1] - mn0);
            float p02 = __expf(S[0][2] - mn1), p03 = __expf(S[0][3] - mn1);
            float p12 = __expf(S[1][2] - mn1), p13 = __expf(S[1][3] - mn1);
            float sum0 = p00 + p01 + p10 + p11;
            float sum1 = p02 + p03 + p12 + p13;
            sum0 += __shfl_xor_sync(0xffffffffu, sum0, 1);
            sum0 += __shfl_xor_sync(0xffffffffu, sum0, 2);
            sum1 += __shfl_xor_sync(0xffffffffu, sum1, 1);
            sum1 += __shfl_xor_sync(0xffffffffu, sum1, 2);
            lrow0 = lrow0 * c0 + sum0;
            lrow1 = lrow1 * c1 + sum1;
            #pragma unroll
            for (int n = 0; n < 8; n++) {
                accO[n][0] *= c0; accO[n][1] *= c0;
                accO[n][2] *= c1; accO[n][3] *= c1;
            }
            uint32_t pA[4] = {
                pack_h2(__float2half_rn(p00), __float2half_rn(p01)),
                pack_h2(__float2half_rn(p02), __float2half_rn(p03)),
                pack_h2(__float2half_rn(p10), __float2half_rn(p11)),
                pack_h2(__float2half_rn(p12), __float2half_rn(p13)) };
            #pragma unroll
            for (int dp = 0; dp < 4; dp++) {
                uint32_t coff = (uint32_t)((dp * 16 + ghalf * 8) * 2);
                uint32_t vf[4];
                LDMX4T(vf, tV + rowoffS + coff);
                MMA16816(accO[dp*2],   pA, vf[0], vf[1]);
                MMA16816(accO[dp*2+1], pA, vf[2], vf[3]);
            }
        }
        float inv0 = 1.0f / lrow0, inv1 = 1.0f / lrow1;
        int rowA = b * Tn + tb * 16 + lr;
        int rowB = rowA + 8;
        #pragma unroll
        for (int n = 0; n < 8; n++) {
            int d = h * 64 + n * 8 + 2 * lq;
            float v0 = accO[n][0] * inv0, v1 = accO[n][1] * inv0;
            float v2 = accO[n][2] * inv1, v3 = accO[n][3] * inv1;
            *(__half2*)(outH + (size_t)rowA * En + d) =
                __halves2half2(__float2half_rn(v0), __float2half_rn(v1));
            *(__half2*)(outH + (size_t)rowB * En + d) =
                __halves2half2(__float2half_rn(v2), __float2half_rn(v3));
        }
    }
}

// ---------------- launch ----------------
extern "C" void kernel_launch(void* const* d_in, const int* in_sizes, int n_in,
                              void* d_out, int out_size)
{
    const float* x      = (const float*)d_in[0];
    const float* ln1_g  = (const float*)d_in[1];
    const float* ln1_b  = (const float*)d_in[2];
    const float* wk     = (const float*)d_in[3];
    const float* wq     = (const float*)d_in[4];
    const float* wv     = (const float*)d_in[5];
    const float* w_proj = (const float*)d_in[6];
    const float* b_proj = (const float*)d_in[7];
    const float* ln2_g  = (const float*)d_in[8];
    const float* ln2_b  = (const float*)d_in[9];
    const float* w1     = (const float*)d_in[10];
    const float* b1     = (const float*)d_in[11];
    const float* w2     = (const float*)d_in[12];
    const float* b2     = (const float*)d_in[13];
    float* out = (float*)d_out;

    void* p;
    __half *h16,*qkv16,*attn16,*ff116,*wqkv,*wp,*w1h,*w2h;
    float *x1;
    cudaGetSymbolAddress(&p, g_h16);    h16    = (__half*)p;
    cudaGetSymbolAddress(&p, g_qkv16);  qkv16  = (__half*)p;
    cudaGetSymbolAddress(&p, g_attn16); attn16 = (__half*)p;
    cudaGetSymbolAddress(&p, g_x1);     x1     = (float*)p;
    cudaGetSymbolAddress(&p, g_ff116);  ff116  = (__half*)p;
    cudaGetSymbolAddress(&p, g_wqkv);   wqkv   = (__half*)p;
    cudaGetSymbolAddress(&p, g_wp);     wp     = (__half*)p;
    cudaGetSymbolAddress(&p, g_w1);     w1h    = (__half*)p;
    cudaGetSymbolAddress(&p, g_w2);     w2h    = (__half*)p;

    cudaFuncSetAttribute(attn_mma_kernel, cudaFuncAttributeMaxDynamicSharedMemorySize, ATTN_SMEM);
    cudaFuncSetAttribute(mma_gemm_kernel, cudaFuncAttributeMaxDynamicSharedMemorySize, GEMM_SMEM);

    // 1) LN1 -> fp16
    ln_kernel<<<Mrows, 256>>>(x, ln1_g, ln1_b, h16);
    // 2) weight conversions (fp16): qkv pack + merged 3x E*E transpose
    pack_qkv_kernel<<<dim3(2, 32, 48), 1024>>>(wk, wq, wv, wqkv);
    tconv3_kernel<<<dim3(32, 32, 3), 1024>>>(w_proj, wp, w1, w1h, w2, w2h);
    // 3) QKV GEMM -> fp16 qkv
    mma_gemm_kernel<<<dim3(QKV_N/128, Mrows/128), 256, GEMM_SMEM>>>(
        h16, wqkv, nullptr, nullptr, 0, nullptr, qkv16, QKV_N);
    // 4) MMA flash attention -> fp16 (2 CTAs/SM)
    attn_mma_kernel<<<Bn * Hn, 256, ATTN_SMEM>>>(qkv16, attn16);
    // 5) proj + bias + residual(x) -> fp32 x1
    mma_gemm_kernel<<<dim3(En/128, Mrows/128), 256, GEMM_SMEM>>>(
        attn16, wp, b_proj, x, 0, x1, nullptr, En);
    // 6) LN2 -> fp16
    ln_kernel<<<Mrows, 256>>>(x1, ln2_g, ln2_b, h16);
    // 7) FFN1 + bias + relu -> fp16
    mma_gemm_kernel<<<dim3(En/128, Mrows/128), 256, GEMM_SMEM>>>(
        h16, w1h, b1, nullptr, 1, nullptr, ff116, En);
    // 8) FFN2 + bias + residual(x1) -> out
    mma_gemm_kernel<<<dim3(En/128, Mrows/128), 256, GEMM_SMEM>>>(
        ff116, w2h, b2, x1, 0, out, nullptr, En);
}

// round 16
// speedup vs baseline: 1.1020x; 1.0283x over previous
#include <cuda_runtime.h>
#include <cuda_fp16.h>
#include <math.h>
#include <stdint.h>

// Problem constants
#define Bn 64
#define Tn 256
#define En 1024
#define Hn 16
#define HDn 64
#define Mrows (Bn*Tn)          // 16384
#define QKV_N (3*En)           // 3072
#define Kdim 1024              // all GEMMs have K=1024

// ---------------- scratch (static device globals; no allocation) ----------------
__device__ __half g_h16[(size_t)Mrows*En];
__device__ __half g_qkv16[(size_t)Mrows*QKV_N];
__device__ __half g_attn16[(size_t)Mrows*En];
__device__ float  g_x1[(size_t)Mrows*En];
__device__ __half g_ff116[(size_t)Mrows*En];
// weights fp16, B-operand layout [N,K] K-major
__device__ __half g_wqkv[(size_t)QKV_N*Kdim];
__device__ __half g_wp[(size_t)En*Kdim];
__device__ __half g_w1[(size_t)En*Kdim];
__device__ __half g_w2[(size_t)En*Kdim];

// ---------------- small helpers ----------------
__device__ __forceinline__ uint32_t smem_u32(const void* p) {
    uint32_t a;
    asm("{ .reg .u64 t; cvta.to.shared.u64 t, %1; cvt.u32.u64 %0, t; }" : "=r"(a) : "l"(p));
    return a;
}
__device__ __forceinline__ uint32_t pack_h2(__half lo, __half hi) {
    __half2 t = __halves2half2(lo, hi);
    return *reinterpret_cast<uint32_t*>(&t);
}

#define CP_ASYNC16(dst, src) \
    asm volatile("cp.async.cg.shared.global [%0], [%1], 16;" :: "r"(dst), "l"(src) : "memory")
#define CP_COMMIT() asm volatile("cp.async.commit_group;" ::: "memory")
#define CP_WAIT0()  asm volatile("cp.async.wait_group 0;" ::: "memory")

#define LDMX4(r, addr) \
    asm volatile("ldmatrix.sync.aligned.m8n8.x4.shared.b16 {%0,%1,%2,%3}, [%4];" \
        : "=r"((r)[0]),"=r"((r)[1]),"=r"((r)[2]),"=r"((r)[3]) : "r"(addr))
#define LDMX4T(r, addr) \
    asm volatile("ldmatrix.sync.aligned.m8n8.x4.trans.shared.b16 {%0,%1,%2,%3}, [%4];" \
        : "=r"((r)[0]),"=r"((r)[1]),"=r"((r)[2]),"=r"((r)[3]) : "r"(addr))

#define MMA16816(d, a, b0, b1) \
    asm volatile("mma.sync.aligned.m16n8k16.row.col.f32.f16.f16.f32 " \
        "{%0,%1,%2,%3},{%4,%5,%6,%7},{%8,%9},{%0,%1,%2,%3};" \
        : "+f"((d)[0]),"+f"((d)[1]),"+f"((d)[2]),"+f"((d)[3]) \
        : "r"((a)[0]),"r"((a)[1]),"r"((a)[2]),"r"((a)[3]), "r"(b0),"r"(b1))

// ---------------- LayerNorm -> fp16 ----------------
__device__ __forceinline__ float block_reduce_sum(float v, float* sbuf) {
    #pragma unroll
    for (int o = 16; o > 0; o >>= 1) v += __shfl_xor_sync(0xffffffffu, v, o);
    int w = threadIdx.x >> 5;
    if ((threadIdx.x & 31) == 0) sbuf[w] = v;
    __syncthreads();
    if (threadIdx.x < 8) {
        float t = sbuf[threadIdx.x];
        #pragma unroll
        for (int o = 4; o > 0; o >>= 1) t += __shfl_xor_sync(0xffu, t, o);
        if (threadIdx.x == 0) sbuf[0] = t;
    }
    __syncthreads();
    float r = sbuf[0];
    __syncthreads();
    return r;
}

__global__ __launch_bounds__(256) void ln_kernel(
    const float* __restrict__ x, const float* __restrict__ g,
    const float* __restrict__ b, __half* __restrict__ oh)
{
    __shared__ float sbuf[8];
    int row = blockIdx.x;
    const float* xr = x + (size_t)row * En;
    int tid = threadIdx.x;
    float4 xv = *(const float4*)(xr + tid * 4);
    float s = xv.x + xv.y + xv.z + xv.w;
    s = block_reduce_sum(s, sbuf);
    float mu = s * (1.0f / En);
    float d0 = xv.x - mu, d1 = xv.y - mu, d2 = xv.z - mu, d3 = xv.w - mu;
    float ss = d0*d0 + d1*d1 + d2*d2 + d3*d3;
    ss = block_reduce_sum(ss, sbuf);
    float rstd = rsqrtf(ss * (1.0f / En) + 1e-5f);
    float4 gv = *(const float4*)(g + tid * 4);
    float4 bv = *(const float4*)(b + tid * 4);
    float o0 = d0 * rstd * gv.x + bv.x;
    float o1 = d1 * rstd * gv.y + bv.y;
    float o2 = d2 * rstd * gv.z + bv.z;
    float o3 = d3 * rstd * gv.w + bv.w;
    size_t base = (size_t)row * En + tid * 4;
    *(__half2*)(oh + base)     = __halves2half2(__float2half_rn(o0), __float2half_rn(o1));
    *(__half2*)(oh + base + 2) = __halves2half2(__float2half_rn(o2), __float2half_rn(o3));
}

// ---------------- merged weight transpose-convert: 3x W[1024,1024] -> B[N,K] fp16 ----------------
__global__ __launch_bounds__(1024) void tconv3_kernel(
    const float* __restrict__ W0, __half* __restrict__ B0,
    const float* __restrict__ W1, __half* __restrict__ B1,
    const float* __restrict__ W2, __half* __restrict__ B2)
{
    __shared__ float tile[32][33];
    const float* W = (blockIdx.z == 0) ? W0 : (blockIdx.z == 1) ? W1 : W2;
    __half* Bh     = (blockIdx.z == 0) ? B0 : (blockIdx.z == 1) ? B1 : B2;
    int tx = threadIdx.x & 31, ty = threadIdx.x >> 5;
    int k = blockIdx.y * 32 + ty, n = blockIdx.x * 32 + tx;
    tile[ty][tx] = W[(size_t)k * En + n];
    __syncthreads();
    int nn = blockIdx.x * 32 + ty, kk = blockIdx.y * 32 + tx;
    Bh[(size_t)nn * Kdim + kk] = __float2half_rn(tile[tx][ty]);
}

// qkv pack: wk/wq/wv [H,E,HD] -> B[3072,1024] rows n = which*1024 + h*64 + d, col e
__global__ __launch_bounds__(1024) void pack_qkv_kernel(
    const float* __restrict__ wk, const float* __restrict__ wq,
    const float* __restrict__ wv, __half* __restrict__ Bh)
{
    __shared__ float tile[32][33];
    int tx = threadIdx.x & 31, ty = threadIdx.x >> 5;
    int wh = blockIdx.z;             // which*16 + h
    int which = wh >> 4, h = wh & 15;
    const float* src = (which == 0) ? wk : (which == 1) ? wq : wv;
    int e = blockIdx.y * 32 + ty;
    int d = blockIdx.x * 32 + tx;
    tile[ty][tx] = src[(size_t)h * (En * HDn) + (size_t)e * HDn + d];
    __syncthreads();
    int n = which * En + h * HDn + blockIdx.x * 32 + ty;
    int ee = blockIdx.y * 32 + tx;
    Bh[(size_t)n * Kdim + ee] = __float2half_rn(tile[tx][ty]);
}

// ---------------- HMMA GEMM: C[M,N] = A[M,1024] @ B[N,1024]^T, fp16 single ----------------
// CTA tile 128x128, 8 warps (2x4), warp tile 64x32.
// K stages of 64 (two 32-wide sub-tiles), 2-stage ping-pong: 16 barriers instead of 32.
#define TPITCH   80
#define TILE_B   (128*TPITCH)     // 10240
#define STAGE_B  (4*TILE_B)       // 40960: A0,B0,A1,B1
#define NSTAGES  (Kdim/64)        // 16
#define GEMM_SMEM (2*STAGE_B)     // 81920

__global__ __launch_bounds__(256, 2) void mma_gemm_kernel(
    const __half* __restrict__ Am, const __half* __restrict__ Bw,
    const float* __restrict__ bias, const float* __restrict__ res, int relu,
    float* __restrict__ outF, __half* __restrict__ outH, int N)
{
    extern __shared__ char smem[];
    uint32_t sb = smem_u32(smem);
    int tid  = threadIdx.x;
    int lane = tid & 31, wid = tid >> 5;
    int wm = wid >> 2, wn = wid & 3;      // warp grid 2x4
    int row0 = blockIdx.y * 128, col0 = blockIdx.x * 128;

    const __half* srcA = Am + (size_t)row0 * Kdim;
    const __half* srcB = Bw + (size_t)col0 * Kdim;

    int id0 = tid, id1 = tid + 256;
    int r0g = id0 >> 2, g0 = id0 & 3;
    int r1g = id1 >> 2, g1 = id1 & 3;
    uint32_t so0 = (uint32_t)(r0g * TPITCH + g0 * 16);
    uint32_t so1 = (uint32_t)(r1g * TPITCH + g1 * 16);
    size_t   go0 = (size_t)r0g * Kdim + g0 * 8;
    size_t   go1 = (size_t)r1g * Kdim + g1 * 8;

    float acc[4][4][4];
    #pragma unroll
    for (int i = 0; i < 4; i++)
        #pragma unroll
        for (int j = 0; j < 4; j++)
            #pragma unroll
            for (int q = 0; q < 4; q++) acc[i][j][q] = 0.0f;

    int rowsel = lane & 15;
    int ghalf  = lane >> 4;
    uint32_t aRowOff = (uint32_t)((wm * 64 + rowsel) * TPITCH);
    uint32_t bRowOff = (uint32_t)((wn * 32 + rowsel) * TPITCH);

    // one stage = K columns [s*64, s*64+64): sub-tile t in {0,1} covers 32 k-cols
    #define LOAD_STAGE(s) do { \
        uint32_t bb = sb + ((s) & 1) * STAGE_B; \
        int k0 = (s) * 64; \
        CP_ASYNC16(bb + 0*TILE_B + so0, srcA + go0 + k0); \
        CP_ASYNC16(bb + 0*TILE_B + so1, srcA + go1 + k0); \
        CP_ASYNC16(bb + 1*TILE_B + so0, srcB + go0 + k0); \
        CP_ASYNC16(bb + 1*TILE_B + so1, srcB + go1 + k0); \
        CP_ASYNC16(bb + 2*TILE_B + so0, srcA + go0 + k0 + 32); \
        CP_ASYNC16(bb + 2*TILE_B + so1, srcA + go1 + k0 + 32); \
        CP_ASYNC16(bb + 3*TILE_B + so0, srcB + go0 + k0 + 32); \
        CP_ASYNC16(bb + 3*TILE_B + so1, srcB + go1 + k0 + 32); \
        CP_COMMIT(); \
    } while (0)

    LOAD_STAGE(0);

    for (int s = 0; s < NSTAGES; s++) {
        CP_WAIT0();                  // only pending group is stage s
        __syncthreads();             // stage (s+1)&1 buffer free + stage s visible
        if (s + 1 < NSTAGES) LOAD_STAGE(s + 1);

        uint32_t stbase = sb + (s & 1) * STAGE_B;
        #pragma unroll
        for (int t = 0; t < 2; t++) {
            uint32_t bb = stbase + t * 2 * TILE_B;
            #pragma unroll
            for (int ks = 0; ks < 2; ks++) {
                uint32_t kOff = (uint32_t)((ks * 2 + ghalf) * 16);
                uint32_t fA[4][4], fB[2][4];
                #pragma unroll
                for (int fm = 0; fm < 4; fm++) {
                    uint32_t ra = bb + aRowOff + (uint32_t)(fm * 16 * TPITCH) + kOff;
                    LDMX4(fA[fm], ra);
                }
                #pragma unroll
                for (int h = 0; h < 2; h++) {
                    uint32_t rb = bb + TILE_B + bRowOff + (uint32_t)(h * 16 * TPITCH) + kOff;
                    LDMX4(fB[h], rb);
                }
                #pragma unroll
                for (int fm = 0; fm < 4; fm++)
                    #pragma unroll
                    for (int fn = 0; fn < 4; fn++) {
                        int h = fn >> 1, s2 = fn & 1;
                        MMA16816(acc[fm][fn], fA[fm], fB[h][s2], fB[h][s2 + 2]);
                    }
            }
        }
    }
    #undef LOAD_STAGE

    // epilogue (no smem use; no barrier needed)
    #pragma unroll
    for (int fm = 0; fm < 4; fm++) {
        #pragma unroll
        for (int fn = 0; fn < 4; fn++) {
            int r = row0 + wm * 64 + fm * 16 + (lane >> 2);
            int cc = col0 + wn * 32 + fn * 8 + 2 * (lane & 3);
            #pragma unroll
            for (int hf = 0; hf < 2; hf++) {
                int rr = r + hf * 8;
                float v0 = acc[fm][fn][hf * 2 + 0];
                float v1 = acc[fm][fn][hf * 2 + 1];
                if (bias) {
                    float2 bv = *(const float2*)(bias + cc);
                    v0 += bv.x; v1 += bv.y;
                }
                if (res) {
                    float2 rv = *(const float2*)(res + (size_t)rr * N + cc);
                    v0 += rv.x; v1 += rv.y;
                }
                if (relu) { v0 = fmaxf(v0, 0.f); v1 = fmaxf(v1, 0.f); }
                if (outF) {
                    *(float2*)(outF + (size_t)rr * N + cc) = make_float2(v0, v1);
                } else {
                    *(__half2*)(outH + (size_t)rr * N + cc) =
                        __halves2half2(__float2half_rn(v0), __float2half_rn(v1));
                }
            }
        }
    }
}

// ---------------- MMA flash attention (scores = K . Q^T per reference) ----------------
// One CTA per (b,h). smem: 3 tiles [256 x 64] fp16, pitch 72 halfs (144B): K, Q, V.
#define APITCHB 144
#define ATILE   (256*APITCHB)   // 36864
#define ATTN_SMEM (3*ATILE)     // 110592

__global__ __launch_bounds__(256, 2) void attn_mma_kernel(
    const __half* __restrict__ qkv16, __half* __restrict__ outH)
{
    extern __shared__ char smem[];
    uint32_t sb = smem_u32(smem);
    int bh = blockIdx.x;
    int b = bh >> 4, h = bh & 15;
    int tid = threadIdx.x, lane = tid & 31, wid = tid >> 5;

    const size_t rowBase = (size_t)(b * Tn) * QKV_N;
    {
        const __half* srcs[3] = {
            qkv16 + rowBase + h * 64,
            qkv16 + rowBase + 1024 + h * 64,
            qkv16 + rowBase + 2048 + h * 64 };
        #pragma unroll
        for (int tl = 0; tl < 3; tl++) {
            uint32_t tb = sb + tl * ATILE;
            const __half* s = srcs[tl];
            #pragma unroll
            for (int i = 0; i < 8; i++) {
                int idx = i * 256 + tid;
                int r = idx >> 3, g = idx & 7;
                CP_ASYNC16(tb + (uint32_t)(r * APITCHB + g * 16), s + (size_t)r * QKV_N + g * 8);
            }
        }
        CP_COMMIT(); CP_WAIT0();
        __syncthreads();
    }
    uint32_t tK = sb, tQ = sb + ATILE, tV = sb + 2*ATILE;

    const float scale = 0.125f;
    int rsel = lane & 15, ghalf = lane >> 4;
    int lr = lane >> 2, lq = lane & 3;

    #pragma unroll
    for (int hb = 0; hb < 2; hb++) {
        int tb = (hb == 0) ? wid : 15 - wid;
        uint32_t kA[4][4];
        {
            uint32_t rowoff = (uint32_t)((tb * 16 + rsel) * APITCHB);
            #pragma unroll
            for (int k = 0; k < 4; k++) {
                uint32_t coff = (uint32_t)((k * 16 + ghalf * 8) * 2);
                LDMX4(kA[k], tK + rowoff + coff);
            }
        }
        float accO[8][4];
        #pragma unroll
        for (int n = 0; n < 8; n++)
            #pragma unroll
            for (int e = 0; e < 4; e++) accO[n][e] = 0.0f;
        float mrow0 = -1e30f, mrow1 = -1e30f, lrow0 = 0.0f, lrow1 = 0.0f;

        for (int sbk = 0; sbk <= tb; sbk++) {
            float S[2][4];
            #pragma unroll
            for (int j = 0; j < 2; j++)
                #pragma unroll
                for (int e = 0; e < 4; e++) S[j][e] = 0.0f;
            uint32_t rowoffS = (uint32_t)((sbk * 16 + rsel) * APITCHB);
            #pragma unroll
            for (int k = 0; k < 4; k++) {
                uint32_t coff = (uint32_t)((k * 16 + ghalf * 8) * 2);
                uint32_t qf[4];
                LDMX4(qf, tQ + rowoffS + coff);
                MMA16816(S[0], kA[k], qf[0], qf[2]);
                MMA16816(S[1], kA[k], qf[1], qf[3]);
            }
            #pragma unroll
            for (int j = 0; j < 2; j++)
                #pragma unroll
                for (int e = 0; e < 4; e++) {
                    float v = S[j][e] * scale;
                    if (sbk == tb) {
                        int row = tb * 16 + lr + ((e >> 1) << 3);
                        int col = sbk * 16 + j * 8 + 2 * lq + (e & 1);
                        if (col > row) v = -1e30f;
                    }
                    S[j][e] = v;
                }
            float mx0 = fmaxf(fmaxf(S[0][0], S[0][1]), fmaxf(S[1][0], S[1][1]));
            float mx1 = fmaxf(fmaxf(S[0][2], S[0][3]), fmaxf(S[1][2], S[1][3]));
            mx0 = fmaxf(mx0, __shfl_xor_sync(0xffffffffu, mx0, 1));
            mx0 = fmaxf(mx0, __shfl_xor_sync(0xffffffffu, mx0, 2));
            mx1 = fmaxf(mx1, __shfl_xor_sync(0xffffffffu, mx1, 1));
            mx1 = fmaxf(mx1, __shfl_xor_sync(0xffffffffu, mx1, 2));
            float mn0 = fmaxf(mrow0, mx0), mn1 = fmaxf(mrow1, mx1);
            float c0 = __expf(mrow0 - mn0), c1 = __expf(mrow1 - mn1);
            mrow0 = mn0; mrow1 = mn1;
            float p00 = __expf(S[0][0] - mn0), p01 = __expf(S[0][1] - mn0);
            float p10 = __expf(S[1][0] - mn0), p11 = __expf(S[1][1] - mn0);
            float p02 = __expf(S[0][2] - mn1), p03 = __expf(S[0][3] - mn1);
            float p12 = __expf(S[1][2] - mn1), p13 = __expf(S[1][3] - mn1);
            float sum0 = p00 + p01 + p10 + p11;
            float sum1 = p02 + p03 + p12 + p13;
            sum0 += __shfl_xor_sync(0xffffffffu, sum0, 1);
            sum0 += __shfl_xor_sync(0xffffffffu, sum0, 2);
            sum1 += __shfl_xor_sync(0xffffffffu, sum1, 1);
            sum1 += __shfl_xor_sync(0xffffffffu, sum1, 2);
            lrow0 = lrow0 * c0 + sum0;
            lrow1 = lrow1 * c1 + sum1;
            #pragma unroll
            for (int n = 0; n < 8; n++) {
                accO[n][0] *= c0; accO[n][1] *= c0;
                accO[n][2] *= c1; accO[n][3] *= c1;
            }
            uint32_t pA[4] = {
                pack_h2(__float2half_rn(p00), __float2half_rn(p01)),
                pack_h2(__float2half_rn(p02), __float2half_rn(p03)),
                pack_h2(__float2half_rn(p10), __float2half_rn(p11)),
                pack_h2(__float2half_rn(p12), __float2half_rn(p13)) };
            #pragma unroll
            for (int dp = 0; dp < 4; dp++) {
                uint32_t coff = (uint32_t)((dp * 16 + ghalf * 8) * 2);
                uint32_t vf[4];
                LDMX4T(vf, tV + rowoffS + coff);
                MMA16816(accO[dp*2],   pA, vf[0], vf[1]);
                MMA16816(accO[dp*2+1], pA, vf[2], vf[3]);
            }
        }
        float inv0 = 1.0f / lrow0, inv1 = 1.0f / lrow1;
        int rowA = b * Tn + tb * 16 + lr;
        int rowB = rowA + 8;
        #pragma unroll
        for (int n = 0; n < 8; n++) {
            int d = h * 64 + n * 8 + 2 * lq;
            float v0 = accO[n][0] * inv0, v1 = accO[n][1] * inv0;
            float v2 = accO[n][2] * inv1, v3 = accO[n][3] * inv1;
            *(__half2*)(outH + (size_t)rowA * En + d) =
                __halves2half2(__float2half_rn(v0), __float2half_rn(v1));
            *(__half2*)(outH + (size_t)rowB * En + d) =
                __halves2half2(__float2half_rn(v2), __float2half_rn(v3));
        }
    }
}

// ---------------- launch ----------------
extern "C" void kernel_launch(void* const* d_in, const int* in_sizes, int n_in,
                              void* d_out, int out_size)
{
    const float* x      = (const float*)d_in[0];
    const float* ln1_g  = (const float*)d_in[1];
    const float* ln1_b  = (const float*)d_in[2];
    const float* wk     = (const float*)d_in[3];
    const float* wq     = (const float*)d_in[4];
    const float* wv     = (const float*)d_in[5];
    const float* w_proj = (const float*)d_in[6];
    const float* b_proj = (const float*)d_in[7];
    const float* ln2_g  = (const float*)d_in[8];
    const float* ln2_b  = (const float*)d_in[9];
    const float* w1     = (const float*)d_in[10];
    const float* b1     = (const float*)d_in[11];
    const float* w2     = (const float*)d_in[12];
    const float* b2     = (const float*)d_in[13];
    float* out = (float*)d_out;

    void* p;
    __half *h16,*qkv16,*attn16,*ff116,*wqkv,*wp,*w1h,*w2h;
    float *x1;
    cudaGetSymbolAddress(&p, g_h16);    h16    = (__half*)p;
    cudaGetSymbolAddress(&p, g_qkv16);  qkv16  = (__half*)p;
    cudaGetSymbolAddress(&p, g_attn16); attn16 = (__half*)p;
    cudaGetSymbolAddress(&p, g_x1);     x1     = (float*)p;
    cudaGetSymbolAddress(&p, g_ff116);  ff116  = (__half*)p;
    cudaGetSymbolAddress(&p, g_wqkv);   wqkv   = (__half*)p;
    cudaGetSymbolAddress(&p, g_wp);     wp     = (__half*)p;
    cudaGetSymbolAddress(&p, g_w1);     w1h    = (__half*)p;
    cudaGetSymbolAddress(&p, g_w2);     w2h    = (__half*)p;

    cudaFuncSetAttribute(attn_mma_kernel, cudaFuncAttributeMaxDynamicSharedMemorySize, ATTN_SMEM);
    cudaFuncSetAttribute(mma_gemm_kernel, cudaFuncAttributeMaxDynamicSharedMemorySize, GEMM_SMEM);

    // 1) LN1 -> fp16
    ln_kernel<<<Mrows, 256>>>(x, ln1_g, ln1_b, h16);
    // 2) weight conversions (fp16): qkv pack + merged 3x E*E transpose
    pack_qkv_kernel<<<dim3(2, 32, 48), 1024>>>(wk, wq, wv, wqkv);
    tconv3_kernel<<<dim3(32, 32, 3), 1024>>>(w_proj, wp, w1, w1h, w2, w2h);
    // 3) QKV GEMM -> fp16 qkv
    mma_gemm_kernel<<<dim3(QKV_N/128, Mrows/128), 256, GEMM_SMEM>>>(
        h16, wqkv, nullptr, nullptr, 0, nullptr, qkv16, QKV_N);
    // 4) MMA flash attention -> fp16 (2 CTAs/SM)
    attn_mma_kernel<<<Bn * Hn, 256, ATTN_SMEM>>>(qkv16, attn16);
    // 5) proj + bias + residual(x) -> fp32 x1
    mma_gemm_kernel<<<dim3(En/128, Mrows/128), 256, GEMM_SMEM>>>(
        attn16, wp, b_proj, x, 0, x1, nullptr, En);
    // 6) LN2 -> fp16
    ln_kernel<<<Mrows, 256>>>(x1, ln2_g, ln2_b, h16);
    // 7) FFN1 + bias + relu -> fp16
    mma_gemm_kernel<<<dim3(En/128, Mrows/128), 256, GEMM_SMEM>>>(
        h16, w1h, b1, nullptr, 1, nullptr, ff116, En);
    // 8) FFN2 + bias + residual(x1) -> out
    mma_gemm_kernel<<<dim3(En/128, Mrows/128), 256, GEMM_SMEM>>>(
        ff116, w2h, b2, x1, 0, out, nullptr, En);
}